// round 11
// baseline (speedup 1.0000x reference)
#include <cuda_runtime.h>
#include <cuda_bf16.h>

#define NUM_CLASSES 1000
#define FEAT_DIM 512
#define BATCH 65536
#define NSLAB 32
#define HIST_THREADS 256
#define THREADS 512
#define WARPS_PER_BLOCK (THREADS / 32)      // 16
#define NBLOCKS (BATCH / WARPS_PER_BLOCK)   // 4096

// Per-block partial histograms, transposed: g_part[class][slab].
// g_cbf: centers quantized to bf16 (1MB). Both fully overwritten every call.
__device__ int g_part[NUM_CLASSES * NSLAB];
__device__ __nv_bfloat16 g_cbf[NUM_CLASSES * FEAT_DIM];

// K1: 32 blocks; private smem histograms -> slab columns; ALSO converts the
// centers to bf16 (grid-stride over float4s). Block 0 zeroes out[0].
__global__ void __launch_bounds__(HIST_THREADS) cl_hist_kernel(
    const long long* __restrict__ labels,
    const float* __restrict__ centers,
    float* __restrict__ out)
{
    __shared__ int h[NUM_CLASSES];
    for (int c = threadIdx.x; c < NUM_CLASSES; c += HIST_THREADS) h[c] = 0;
    if (blockIdx.x == 0 && threadIdx.x == 0) out[0] = 0.0f;
    __syncthreads();

    const longlong2* lab2 =
        reinterpret_cast<const longlong2*>(labels + (size_t)blockIdx.x * (BATCH / NSLAB));
#pragma unroll
    for (int i = 0; i < 4; i++) {
        longlong2 v = lab2[threadIdx.x * 4 + i];
        atomicAdd(&h[(int)v.x], 1);
        atomicAdd(&h[(int)v.y], 1);
    }

    // Convert centers f32 -> bf16 while the histogram settles.
    const float4* c4 = reinterpret_cast<const float4*>(centers);
    uint2* dst = reinterpret_cast<uint2*>(g_cbf);
    for (int i = blockIdx.x * HIST_THREADS + threadIdx.x;
         i < NUM_CLASSES * FEAT_DIM / 4;
         i += NSLAB * HIST_THREADS) {
        float4 v = c4[i];
        __nv_bfloat162 lo = __floats2bfloat162_rn(v.x, v.y);
        __nv_bfloat162 hi = __floats2bfloat162_rn(v.z, v.w);
        uint2 o;
        o.x = *reinterpret_cast<unsigned int*>(&lo);
        o.y = *reinterpret_cast<unsigned int*>(&hi);
        dst[i] = o;
    }
    __syncthreads();

    int b = blockIdx.x;
    for (int c = threadIdx.x; c < NUM_CLASSES; c += HIST_THREADS)
        g_part[c * NSLAB + b] = h[c];
}

// K2: R5's proven geometry (512 thr, ~32 regs, ~90% occ), but center reads
// are bf16 (uint2 per lane-step) -> center L2 traffic halves (128->64MB),
// dropping total LTS traffic from 256MB to 192MB. Count via L1-hot slab
// line; one un-fenced atomicAdd(out) per block. Replay-safe (no scratch
// mutation in this kernel).
__global__ void __launch_bounds__(THREADS) cl_main_kernel(
    const float* __restrict__ features,
    const long long* __restrict__ labels,
    float* __restrict__ out)
{
    __shared__ float red[WARPS_PER_BLOCK];

    int warp = threadIdx.x >> 5;
    int lane = threadIdx.x & 31;
    int row = blockIdx.x * WARPS_PER_BLOCK + warp;

    int lab = (int)labels[row];  // warp-uniform broadcast load

    int cnt = __ldg(&g_part[lab * NSLAB + lane]);

    const float4* frow = reinterpret_cast<const float4*>(features + (size_t)row * FEAT_DIM);
    const uint2* crow = reinterpret_cast<const uint2*>(g_cbf + (size_t)lab * FEAT_DIM);

    float acc = 0.0f;
#pragma unroll
    for (int i = 0; i < 4; i++) {
        float4 a = __ldcs(frow + lane + i * 32);  // evict-first feature stream
        uint2 cb = __ldg(crow + lane + i * 32);   // bf16 centers, L2/L1-resident
        __nv_bfloat162 c01 = *reinterpret_cast<__nv_bfloat162*>(&cb.x);
        __nv_bfloat162 c23 = *reinterpret_cast<__nv_bfloat162*>(&cb.y);
        float2 f01 = __bfloat1622float2(c01);
        float2 f23 = __bfloat1622float2(c23);
        float dx = a.x - f01.x;
        float dy = a.y - f01.y;
        float dz = a.z - f23.x;
        float dw = a.w - f23.y;
        acc += dx * dx + dy * dy + dz * dz + dw * dw;
    }

#pragma unroll
    for (int o = 16; o; o >>= 1) {
        acc += __shfl_xor_sync(0xffffffffu, acc, o);
        cnt += __shfl_xor_sync(0xffffffffu, cnt, o);
    }

    if (lane == 0) {
        float w = __fdividef(1.0f, (float)cnt * (float)FEAT_DIM) * (1.0f / (float)BATCH);
        red[warp] = acc * w;
    }
    __syncthreads();

    if (warp == 0) {
        float v = (lane < WARPS_PER_BLOCK) ? red[lane] : 0.0f;
#pragma unroll
        for (int o = 8; o; o >>= 1)
            v += __shfl_xor_sync(0xffffffffu, v, o);
        if (lane == 0)
            atomicAdd(out, v);
    }
}

extern "C" void kernel_launch(void* const* d_in, const int* in_sizes, int n_in,
                              void* d_out, int out_size) {
    const float* features = (const float*)d_in[0];
    const float* centers = (const float*)d_in[1];
    const long long* labels = (const long long*)d_in[2];
    float* out = (float*)d_out;

    cl_hist_kernel<<<NSLAB, HIST_THREADS>>>(labels, centers, out);
    cl_main_kernel<<<NBLOCKS, THREADS>>>(features, labels, out);
}